// round 13
// baseline (speedup 1.0000x reference)
#include <cuda_runtime.h>

#define BATCH 8
#define CH 128
#define HH 128
#define WW 128
#define KW 9
#define HWC (HH * WW * CH)
#define NCTA 128
#define NTHR 256
#define GRP 16              // CTAs per batch barrier group
#define AROW 130            // u64 row stride in SMEM (padded: conflict-free)
#define SMEM_BYTES (2 * 72 * AROW * 8)   // w_s + a_s = 149760 B

// fp32 working state in (b, i, j, c) layout. 64 MB static device scratch.
__device__ float g_y[BATCH * HH * WW * CH];
// Per-batch barrier slots: g_bars[b][s]. Batches on separate 512B regions.
// Protocol restores everything to 0 before kernel exit (graph-replay safe).
__device__ int g_bars[BATCH][128];
__device__ int g_doneb[BATCH * 32];

typedef unsigned long long u64;

__device__ __forceinline__ u64 pack2(float x) {
    u64 r;
    asm("mov.b64 %0, {%1, %1};" : "=l"(r) : "f"(x));
    return r;
}
__device__ __forceinline__ u64 packf2(float x, float y) {
    u64 r;
    asm("mov.b64 %0, {%1, %2};" : "=l"(r) : "f"(x), "f"(y));
    return r;
}
__device__ __forceinline__ void fma2(u64& d, u64 a, u64 b) {
    asm("fma.rn.f32x2 %0, %1, %2, %0;" : "+l"(d) : "l"(a), "l"(b));
}
__device__ __forceinline__ float2 unpack2(u64 v) {
    float2 f;
    asm("mov.b64 {%0, %1}, %2;" : "=f"(f.x), "=f"(f.y) : "l"(v));
    return f;
}

// ---------------------------------------------------------------------------
// Transpose in: x (B,C,H,W) -> g_y (B,H,W,C)
// ---------------------------------------------------------------------------
__global__ void t_in_kernel(const float* __restrict__ x) {
    __shared__ float tile[32][33];
    int b = blockIdx.z >> 7;
    int h = blockIdx.z & 127;
    int w0 = blockIdx.x * 32;
    int c0 = blockIdx.y * 32;
    int tx = threadIdx.x, ty = threadIdx.y;
#pragma unroll
    for (int k = 0; k < 32; k += 8) {
        int c = c0 + ty + k;
        tile[ty + k][tx] = x[(((b * CH + c) * HH + h) * WW) + w0 + tx];
    }
    __syncthreads();
#pragma unroll
    for (int k = 0; k < 32; k += 8) {
        int w = w0 + ty + k;
        g_y[(((b * HH + h) * WW + w) * CH) + c0 + tx] = tile[tx][ty + k];
    }
}

// ---------------------------------------------------------------------------
// Transpose out: g_y (B,H,W,C) -> out (B,C,H,W)
// ---------------------------------------------------------------------------
__global__ void t_out_kernel(float* __restrict__ o) {
    __shared__ float tile[32][33];
    int b = blockIdx.z >> 7;
    int h = blockIdx.z & 127;
    int w0 = blockIdx.x * 32;
    int c0 = blockIdx.y * 32;
    int tx = threadIdx.x, ty = threadIdx.y;
#pragma unroll
    for (int k = 0; k < 32; k += 8) {
        int w = w0 + ty + k;
        tile[ty + k][tx] = g_y[(((b * HH + h) * WW + w) * CH) + c0 + tx];
    }
    __syncthreads();
#pragma unroll
    for (int k = 0; k < 32; k += 8) {
        int c = c0 + ty + k;
        o[(((b * CH + c) * HH + h) * WW) + w0 + tx] = tile[tx][ty + k];
    }
}

// ---------------------------------------------------------------------------
// Persistent per-direction scan kernel. 127 steps; per-batch 16-CTA barriers.
// CTA (cox, b, mh): co tile 16 ch, batch b, m half 64 positions.
// Weights resident in SMEM as f32x2 co-pairs: w_s[(t*8+cop)*AROW + ci].
// Prev line staged per step duplicated: a_s[r*AROW + ci] = (v,v).
// 256 threads: thread (cop = tid&7, mg = tid>>3 in 0..31) computes
// m = mstart + mg + {0, 32}, co pair co0 + 2*cop.
// Hot loop per ci-pair: 3x LDS.128 + 4x FFMA2 (2 warps/SMSP hide LDS lat).
// ---------------------------------------------------------------------------
__global__ void __launch_bounds__(NTHR, 1) scan_kernel(
    const float* __restrict__ Kw, int first, int dir, int stride_p, int stride_m) {
    extern __shared__ u64 sm[];
    u64* w_s = sm;                 // 72*AROW u64
    u64* a_s = sm + 72 * AROW;     // 72*AROW u64

    const int tid = threadIdx.x;
    const int bx = blockIdx.x;
    const int cox = bx & 7;
    const int b = (bx >> 3) & 7;
    const int mh = bx >> 6;
    const int co0 = cox * 16;
    const int mstart = mh * 64;
    const int cop = tid & 7;    // co pair 0..7
    const int mg = tid >> 3;    // 0..31
    const bool leader = (cox == 0 && mh == 0);

    // Stage weights once per direction: pack co pairs into u64.
    for (int idx = tid; idx < KW * 8 * CH; idx += NTHR) {
        int t = idx >> 10;
        int rem = idx & 1023;
        int cp = rem >> 7;
        int ci = rem & 127;
        float2 wv = *(const float2*)(Kw + (size_t)(t * CH + ci) * CH + co0 + 2 * cp);
        w_s[(t * 8 + cp) * AROW + ci] = packf2(wv.x, wv.y);
    }
    __syncthreads();

    float* ybase = g_y + (size_t)b * HWC;

    for (int s = 0; s < 127; ++s) {
        int cur = first + dir * s;
        int prev = cur - dir;

        // Stage prev line (72 conv-positions incl. halo, duplicated f32x2).
        const float* pb = ybase + (size_t)prev * stride_p;
        for (int j = tid; j < 72 * 64; j += NTHR) {
            int r = j >> 6;       // 0..71
            int c = j & 63;       // float2 chunk; ci = 2c
            int pos = mstart - 4 + r;
            float2 v = make_float2(0.f, 0.f);
            if (pos >= 0 && pos < 128)
                v = *(const float2*)(pb + (size_t)pos * stride_m + 2 * c);
            ulonglong2 d;
            d.x = pack2(v.x);
            d.y = pack2(v.y);
            *(ulonglong2*)(a_s + r * AROW + 2 * c) = d;
        }
        __syncthreads();

        u64 acc0 = 0, acc1 = 0;
        for (int t = 0; t < KW; ++t) {
            const u64* wr = w_s + (t * 8 + cop) * AROW;
            const u64* ar0 = a_s + (mg + t) * AROW;
            const u64* ar1 = ar0 + 32 * AROW;
#pragma unroll 8
            for (int ci = 0; ci < CH; ci += 2) {
                ulonglong2 wv = *(const ulonglong2*)(wr + ci);
                ulonglong2 v0 = *(const ulonglong2*)(ar0 + ci);
                ulonglong2 v1 = *(const ulonglong2*)(ar1 + ci);
                fma2(acc0, v0.x, wv.x);
                fma2(acc1, v1.x, wv.x);
                fma2(acc0, v0.y, wv.y);
                fma2(acc1, v1.y, wv.y);
            }
        }

        // RMW output: cur line += relu(acc)
        float* cb = ybase + (size_t)cur * stride_p;
        int co = co0 + cop * 2;
        {
            int m = mstart + mg;
            float2* op = (float2*)(cb + (size_t)m * stride_m + co);
            float2 old = *op;
            float2 rr = unpack2(acc0);
            old.x += fmaxf(rr.x, 0.f);
            old.y += fmaxf(rr.y, 0.f);
            *op = old;
        }
        {
            int m = mstart + mg + 32;
            float2* op = (float2*)(cb + (size_t)m * stride_m + co);
            float2 old = *op;
            float2 rr = unpack2(acc1);
            old.x += fmaxf(rr.x, 0.f);
            old.y += fmaxf(rr.y, 0.f);
            *op = old;
        }

        // Per-batch barrier among the 16 CTAs of batch b (steps 0..125).
        // Slot s-1 is zeroed by the batch leader after slot s completes.
        if (s < 126) {
            __threadfence();
            __syncthreads();
            if (tid == 0) {
                atomicAdd(&g_bars[b][s], 1);
                while (*(volatile int*)&g_bars[b][s] < GRP) { }
                __threadfence();
            }
            __syncthreads();
            if (leader && tid == 0 && s > 0) g_bars[b][s - 1] = 0;
        }
    }

    // End protocol (per batch): last CTA of the batch arrives, then the batch
    // leader resets the remaining slot + done counter. Safe: arrival happens
    // only after this CTA fully passed barrier slot 125.
    __threadfence();
    __syncthreads();
    if (tid == 0) {
        atomicAdd(&g_doneb[b * 32], 1);
        if (leader) {
            while (*(volatile int*)&g_doneb[b * 32] < GRP) { }
            g_bars[b][125] = 0;
            __threadfence();
            g_doneb[b * 32] = 0;
            __threadfence();
        }
    }
}

// ---------------------------------------------------------------------------
extern "C" void kernel_launch(void* const* d_in, const int* in_sizes, int n_in,
                              void* d_out, int out_size) {
    const float* x   = (const float*)d_in[0];
    const float* ktd = (const float*)d_in[1];
    const float* kdt = (const float*)d_in[2];
    const float* klr = (const float*)d_in[3];
    const float* krl = (const float*)d_in[4];

    cudaFuncSetAttribute(scan_kernel, cudaFuncAttributeMaxDynamicSharedMemorySize,
                         SMEM_BYTES);

    dim3 tb(32, 8);
    dim3 tg(WW / 32, CH / 32, BATCH * HH);
    t_in_kernel<<<tg, tb>>>(x);

    const int ROW = WW * CH;  // 16384
    // Top-down: scan i (stride_p=ROW), conv along j (stride_m=CH)
    scan_kernel<<<NCTA, NTHR, SMEM_BYTES>>>(ktd, 1, 1, ROW, CH);
    // Bottom-up
    scan_kernel<<<NCTA, NTHR, SMEM_BYTES>>>(kdt, HH - 2, -1, ROW, CH);
    // Left-right: scan j (stride_p=CH), conv along i (stride_m=ROW)
    scan_kernel<<<NCTA, NTHR, SMEM_BYTES>>>(klr, 1, 1, CH, ROW);
    // Right-left
    scan_kernel<<<NCTA, NTHR, SMEM_BYTES>>>(krl, WW - 2, -1, CH, ROW);

    t_out_kernel<<<tg, tb>>>((float*)d_out);
}